// round 14
// baseline (speedup 1.0000x reference)
#include <cuda_runtime.h>
#include <cuda_bf16.h>
#include <cstdint>

#define TOK   256
#define INF   4096
#define OUTF  4096
#define NOUT  32

#define NCTA    148
#define NUNITS  2048            // (nt in [0,64)) x (k in [0,32))
#define STAGES  4

#define AHALF   16384           // one A block: 128m x 128k int8
#define BSZ     8192            // one B block: 64n x 128k int8
#define STG_SZ  40960           // A0 + A1 + B per stage
#define SA_OFF(s) ((s) * STG_SZ)
#define MBF_OFF  (STG_SZ * STAGES)          // 163840: full[4]
#define MBE_OFF  (MBF_OFF + 32)             // empty[4]
#define SMEM_TOTAL (MBF_OFF + 128)

// ---------------- scratch (no cudaMalloc allowed) ----------------
__device__ __align__(128) int8_t g_xq[TOK * INF];   // A blocks (1MB)
__device__ float g_xs[TOK];
__device__ int   g_qcnt;    // quantized rows done (0..256)
__device__ int   g_pfcnt;   // prefill blocks done (0..256)

__device__ __forceinline__ uint32_t smem_to_u32(const void* p) {
    uint32_t a;
    asm("{ .reg .u64 t; cvta.to.shared.u64 t, %1; cvt.u32.u64 %0, t; }" : "=r"(a) : "l"(p));
    return a;
}
__device__ __forceinline__ int ld_acq_gpu(const int* p) {
    int v; asm volatile("ld.acquire.gpu.global.s32 %0, [%1];" : "=r"(v) : "l"(p) : "memory"); return v;
}
__device__ __forceinline__ void red_rel_gpu(int* p, int v) {
    asm volatile("red.release.gpu.global.add.s32 [%0], %1;" :: "l"(p), "r"(v) : "memory");
}

#define MBARRIER_INIT(mbar, count) \
    asm volatile("mbarrier.init.shared.b64 [%0], %1;" :: "r"((uint32_t)(mbar)), "r"((uint32_t)(count)) : "memory")
#define MBARRIER_ARRIVE(mbar) \
    asm volatile("mbarrier.arrive.release.cta.shared.b64 _, [%0];" :: "r"((uint32_t)(mbar)) : "memory")
#define MBARRIER_EXPECT_TX(mbar, bytes) \
    asm volatile("mbarrier.arrive.expect_tx.shared.b64 _, [%0], %1;" :: "r"((uint32_t)(mbar)), "r"((uint32_t)(bytes)) : "memory")
#define BULK_G2S(dst, src, bytes, mbar) \
    asm volatile("cp.async.bulk.shared::cluster.global.mbarrier::complete_tx::bytes [%0], [%1], %2, [%3];" \
        :: "r"((uint32_t)(dst)), "l"(src), "r"((uint32_t)(bytes)), "r"((uint32_t)(mbar)) : "memory")
#define FENCE_PROXY_ASYNC() asm volatile("fence.proxy.async;" ::: "memory")

#define MBARRIER_WAIT_PARITY(mbar_smem_addr, phase_parity) do { \
    uint32_t _mbar = (uint32_t)(mbar_smem_addr); \
    uint32_t _parity = (uint32_t)(phase_parity); \
    uint32_t _done; \
    asm volatile("{\n\t.reg .pred p;\n\t" \
        "mbarrier.try_wait.parity.acquire.cta.shared::cta.b64 p, [%1], %2;\n\t" \
        "selp.b32 %0, 1, 0, p;\n\t}" : "=r"(_done) : "r"(_mbar), "r"(_parity) : "memory"); \
    if (!_done) { \
        asm volatile("{\n\t.reg .pred P1;\n\t" \
            "WAIT_LOOP_%=:\n\t" \
            "mbarrier.try_wait.parity.acquire.cta.shared::cta.b64 P1, [%0], %1, 0x989680;\n\t" \
            "@P1 bra.uni WAIT_DONE_%=;\n\t" \
            "bra.uni WAIT_LOOP_%=;\n\t" \
            "WAIT_DONE_%=:\n\t}" :: "r"(_mbar), "r"(_parity) : "memory"); \
    } \
} while (0)

// ---------------- reset counters (graph-replayed each launch) ----------------
__global__ void reset_kernel() { g_qcnt = 0; g_pfcnt = 0; }

// ---------------- fused persistent kernel ----------------
// 148 CTAs x 640 threads (20 warps). Warps 0-15: pure IMMA consumers
// (4m x 4n over m256 x n64). Warps 16-19: producers -- warp 16 lane 0 issues
// TMA for A; each producer warp packs 16 B rows (w int32 -> smem int8 swizzled).
__global__ __launch_bounds__(640, 1) void fused_kernel(const float* __restrict__ x,
                                                       const int* __restrict__ w,
                                                       const int* __restrict__ oidx,
                                                       const float* __restrict__ ow,
                                                       const float* __restrict__ bias,
                                                       const float* __restrict__ wscale,
                                                       float* __restrict__ out) {
    extern __shared__ char smem[];
    const uint32_t sb = smem_to_u32(smem);
    const int tid = threadIdx.x;
    const int lane = tid & 31, wid = tid >> 5;
    const int bid = blockIdx.x;

    const int g0 = (int)(((long long)bid * NUNITS) / NCTA);
    const int g1 = (int)(((long long)(bid + 1) * NUNITS) / NCTA);
    const int nunits = g1 - g0;

    __shared__ float s_red[8];
    __shared__ float s_scale;
    __shared__ int   s_oi[NOUT];
    __shared__ float s_owT[NOUT * 128];
    __shared__ float s_xo[32 * NOUT];
    __shared__ float s_b[128];

    if (tid == 0) {
#pragma unroll
        for (int s = 0; s < STAGES; s++) {
            MBARRIER_INIT(sb + MBF_OFF + s * 8, 5);    // 1 expect_tx + 4 pack-warp arrivals
            MBARRIER_INIT(sb + MBE_OFF + s * 8, 512);  // all consumer threads
        }
    }
    if (tid < NOUT) s_oi[tid] = oidx[tid];
    __syncthreads();

    // ================= prologue (threads < 256 active) =================
    const int nrows = 1 + ((bid + NCTA) < TOK ? 1 : 0);
    for (int rr = 0; rr < nrows; rr++) {
        const int r = bid + rr * NCTA;
        float4 f[4];
        if (tid < 256) {
            const float4* xr = (const float4*)(x + (size_t)r * INF);
#pragma unroll
            for (int t = 0; t < 4; t++) f[t] = xr[tid * 4 + t];
            const int kbase = tid * 16;
            unsigned mz = 0;
#pragma unroll
            for (int j = 0; j < NOUT; j++) {
                unsigned d = (unsigned)(s_oi[j] - kbase);
                if (d < 16u) mz |= 1u << d;
            }
#pragma unroll
            for (int t = 0; t < 4; t++) {
                if (mz & (1u << (t * 4 + 0))) f[t].x = 0.0f;
                if (mz & (1u << (t * 4 + 1))) f[t].y = 0.0f;
                if (mz & (1u << (t * 4 + 2))) f[t].z = 0.0f;
                if (mz & (1u << (t * 4 + 3))) f[t].w = 0.0f;
            }
            float mx = 0.0f;
#pragma unroll
            for (int t = 0; t < 4; t++)
                mx = fmaxf(mx, fmaxf(fmaxf(fabsf(f[t].x), fabsf(f[t].y)),
                                     fmaxf(fabsf(f[t].z), fabsf(f[t].w))));
#pragma unroll
            for (int d = 16; d > 0; d >>= 1) mx = fmaxf(mx, __shfl_xor_sync(0xFFFFFFFFu, mx, d));
            if (lane == 0 && wid < 8) s_red[wid] = mx;
        }
        __syncthreads();
        if (tid == 0) {
            float m = s_red[0];
#pragma unroll
            for (int i = 1; i < 8; i++) m = fmaxf(m, s_red[i]);
            s_scale = m;
            g_xs[r] = m;
        }
        __syncthreads();
        if (tid < 256) {
            const float r127 = 127.0f / fmaxf(s_scale, 1e-8f);
            uint32_t pk[4];
#pragma unroll
            for (int t = 0; t < 4; t++) {
                int q0 = min(max(__float2int_rn(f[t].x * r127), -127), 127);
                int q1 = min(max(__float2int_rn(f[t].y * r127), -127), 127);
                int q2 = min(max(__float2int_rn(f[t].z * r127), -127), 127);
                int q3 = min(max(__float2int_rn(f[t].w * r127), -127), 127);
                uint32_t p0 = __byte_perm((uint32_t)q0, (uint32_t)q1, 0x0040);
                uint32_t p1 = __byte_perm((uint32_t)q2, (uint32_t)q3, 0x0040);
                pk[t] = __byte_perm(p0, p1, 0x5410);
            }
            const int mt = r >> 7, rw = r & 127;
            const int cb = tid >> 3, cp = tid & 7;
            int8_t* dst = g_xq + ((size_t)(mt * 32 + cb) << 14) + rw * 128 + (((cp ^ (rw & 7))) << 4);
            *(uint4*)dst = make_uint4(pk[0], pk[1], pk[2], pk[3]);
        }
    }
    __syncthreads();
    if (tid == 0) red_rel_gpu(&g_qcnt, nrows);

    // ---- outlier + bias prefill blocks bid, bid+148 ----
    for (int ib = 0; ib < nrows; ib++) {
        const int idx = bid + ib * NCTA;
        const int obase = (idx & 31) * 128;
        const int tbase = (idx >> 5) * 32;
        if (tid < 128) s_b[tid] = bias[obase + tid];
        if (tid < 256) {
#pragma unroll
            for (int t = 0; t < 4; t++) {
                int i = tid + t * 256;
                int o = i >> 3, j4 = i & 7;
                float4 fv = ((const float4*)ow)[(size_t)obase * 8 + i];
                s_owT[(j4 * 4 + 0) * 128 + o] = fv.x;
                s_owT[(j4 * 4 + 1) * 128 + o] = fv.y;
                s_owT[(j4 * 4 + 2) * 128 + o] = fv.z;
                s_owT[(j4 * 4 + 3) * 128 + o] = fv.w;
            }
#pragma unroll
            for (int t = 0; t < 4; t++) {
                int i = tid + t * 256;
                int r = i >> 5, j = i & 31;
                s_xo[i] = x[(size_t)(tbase + r) * INF + s_oi[j]];
            }
        }
        __syncthreads();
        if (tid < 256) {
            const int ty = tid >> 5, tx = tid & 31;
            float acc[4][4];
#pragma unroll
            for (int tt = 0; tt < 4; tt++)
#pragma unroll
                for (int c = 0; c < 4; c++) acc[tt][c] = s_b[tx + c * 32];
#pragma unroll
            for (int j = 0; j < NOUT; j++) {
                float wv[4];
#pragma unroll
                for (int c = 0; c < 4; c++) wv[c] = s_owT[j * 128 + tx + c * 32];
#pragma unroll
                for (int tt = 0; tt < 4; tt++) {
                    float xv = s_xo[(ty * 4 + tt) * NOUT + j];
#pragma unroll
                    for (int c = 0; c < 4; c++) acc[tt][c] += xv * wv[c];
                }
            }
#pragma unroll
            for (int tt = 0; tt < 4; tt++)
#pragma unroll
                for (int c = 0; c < 4; c++)
                    out[(size_t)(tbase + ty * 4 + tt) * OUTF + obase + tx + c * 32] = acc[tt][c];
        }
        __syncthreads();
    }
    if (tid == 0) red_rel_gpu(&g_pfcnt, nrows);

    // ================= main phase =================
    if (wid >= 16) {
        // ---- producer warps 16-19: A via TMA (w16 l0), B packed 16 rows/warp ----
        const int rbase = (wid - 16) * 16;
        if (wid == 16 && lane == 0) {
            while (ld_acq_gpu(&g_qcnt) != TOK) __nanosleep(64);
        }
        __syncwarp();
        FENCE_PROXY_ASYNC();

        const uint32_t lcol = ((uint32_t)lane & 3) * 4;
        const uint32_t lgrp = (uint32_t)lane >> 2;

#pragma unroll 1
        for (int it = 0; it < nunits; it++) {
            const int g = g0 + it;
            const int fs = it & (STAGES - 1);
            const int nt = g >> 5, k = g & 31;
            if (it >= STAGES) {
                if (lane == 0) MBARRIER_WAIT_PARITY(sb + MBE_OFF + fs * 8, ((it >> 2) - 1) & 1);
                __syncwarp();
            }
            const uint32_t mb = sb + MBF_OFF + fs * 8;
            if (wid == 16 && lane == 0) {
                MBARRIER_EXPECT_TX(mb, 2 * AHALF);
                BULK_G2S(sb + SA_OFF(fs),         g_xq + ((size_t)k << 14),        AHALF, mb);
                BULK_G2S(sb + SA_OFF(fs) + AHALF, g_xq + ((size_t)(32 + k) << 14), AHALF, mb);
            }
            // pack this warp's 16 B rows: 16 LDG.128 in flight, then 16 STS.32
            const int* wsrc = w + (size_t)(nt * 64 + rbase) * INF + k * 128;
            const uint32_t bstage = sb + SA_OFF(fs) + 2 * AHALF;
            int4 v[16];
#pragma unroll
            for (int i = 0; i < 16; i++)
                v[i] = ((const int4*)(wsrc + (size_t)i * INF))[lane];
#pragma unroll
            for (int i = 0; i < 16; i++) {
                const int r = rbase + i;
                uint32_t pk = __byte_perm(
                    __byte_perm((uint32_t)v[i].x, (uint32_t)v[i].y, 0x0040),
                    __byte_perm((uint32_t)v[i].z, (uint32_t)v[i].w, 0x0040), 0x5410);
                uint32_t off = (uint32_t)r * 128 + ((lgrp ^ (uint32_t)(r & 7)) << 4) + lcol;
                asm volatile("st.shared.b32 [%0], %1;" :: "r"(bstage + off), "r"(pk) : "memory");
            }
            __syncwarp();
            if (lane == 0) MBARRIER_ARRIVE(mb);   // release: this warp's STS visible at flip
        }
    } else {
        // ---- consumers: pure IMMA loop, 16 warps (4m x 4n over m256 x n64) ----
        const int wm = wid >> 2, wn = wid & 3;
        const float inv = 1.0f / 16129.0f;
        const int grp = lane >> 2, qid = lane & 3;
        bool pfok = false;

        int acc[4][2][4];
#pragma unroll
        for (int i = 0; i < 4; i++)
#pragma unroll
            for (int j = 0; j < 2; j++)
#pragma unroll
                for (int q = 0; q < 4; q++) acc[i][j][q] = 0;

#pragma unroll 1
        for (int c = 0; c < nunits; c++) {
            const int g = g0 + c;
            const int s = c & (STAGES - 1);
            MBARRIER_WAIT_PARITY(sb + MBF_OFF + s * 8, (c >> 2) & 1);

#pragma unroll
            for (int ksl = 0; ksl < 4; ksl++) {
                uint32_t a[4][4];
#pragma unroll
                for (int mf = 0; mf < 4; mf++) {
                    int absrow = wm * 64 + mf * 16 + (lane & 15);
                    int blk = absrow >> 7, inner = absrow & 127;
                    int kc = 2 * ksl + (lane >> 4);
                    uint32_t ad = sb + SA_OFF(s) + blk * AHALF +
                                  (uint32_t)(inner * 128 + ((kc ^ (inner & 7)) << 4));
                    asm volatile("ldmatrix.sync.aligned.m8n8.x4.shared.b16 {%0,%1,%2,%3}, [%4];"
                        : "=r"(a[mf][0]), "=r"(a[mf][1]), "=r"(a[mf][2]), "=r"(a[mf][3])
                        : "r"(ad));
                }
                uint32_t b[4];
                {
                    int n = wn * 16 + (lane & 7) + ((lane >> 4) << 3);
                    int kc = 2 * ksl + ((lane >> 3) & 1);
                    uint32_t bd = sb + SA_OFF(s) + 2 * AHALF +
                                  (uint32_t)(n * 128 + ((kc ^ (n & 7)) << 4));
                    asm volatile("ldmatrix.sync.aligned.m8n8.x4.shared.b16 {%0,%1,%2,%3}, [%4];"
                        : "=r"(b[0]), "=r"(b[1]), "=r"(b[2]), "=r"(b[3])
                        : "r"(bd));
                }
#pragma unroll
                for (int mf = 0; mf < 4; mf++)
#pragma unroll
                    for (int nf = 0; nf < 2; nf++) {
                        asm volatile(
                            "mma.sync.aligned.m16n8k32.row.col.s32.s8.s8.s32 "
                            "{%0,%1,%2,%3}, {%4,%5,%6,%7}, {%8,%9}, {%0,%1,%2,%3};"
                            : "+r"(acc[mf][nf][0]), "+r"(acc[mf][nf][1]),
                              "+r"(acc[mf][nf][2]), "+r"(acc[mf][nf][3])
                            : "r"(a[mf][0]), "r"(a[mf][1]), "r"(a[mf][2]), "r"(a[mf][3]),
                              "r"(b[nf * 2]), "r"(b[nf * 2 + 1]));
                    }
            }
            MBARRIER_ARRIVE(sb + MBE_OFF + s * 8);

            // ---- epilogue at nt boundary or range end ----
            if (c + 1 == nunits || ((g + 1) & 31) == 0) {
                if (!pfok) {
                    while (ld_acq_gpu(&g_pfcnt) != 256) __nanosleep(64);
                    pfok = true;
                }
                const int nbase = (g >> 5) * 64;
#pragma unroll
                for (int mf = 0; mf < 4; mf++) {
                    const int m0 = wm * 64 + mf * 16 + grp;
                    const float s0 = g_xs[m0] * inv;
                    const float s1 = g_xs[m0 + 8] * inv;
#pragma unroll
                    for (int nf = 0; nf < 2; nf++) {
                        const int o = nbase + wn * 16 + nf * 8 + qid * 2;
                        const float2 wsv = *(const float2*)(wscale + o);
                        float* p0 = out + (size_t)m0 * OUTF + o;
                        float* p1 = out + (size_t)(m0 + 8) * OUTF + o;
                        atomicAdd(p0,     (float)acc[mf][nf][0] * (s0 * wsv.x));
                        atomicAdd(p0 + 1, (float)acc[mf][nf][1] * (s0 * wsv.y));
                        atomicAdd(p1,     (float)acc[mf][nf][2] * (s1 * wsv.x));
                        atomicAdd(p1 + 1, (float)acc[mf][nf][3] * (s1 * wsv.y));
                    }
                }
#pragma unroll
                for (int i = 0; i < 4; i++)
#pragma unroll
                    for (int j = 0; j < 2; j++)
#pragma unroll
                        for (int q = 0; q < 4; q++) acc[i][j][q] = 0;
            }
        }
    }
}

// ---------------- launch ----------------
extern "C" void kernel_launch(void* const* d_in, const int* in_sizes, int n_in,
                              void* d_out, int out_size) {
    const float* x    = (const float*)d_in[0];
    const int*   w    = (const int*)d_in[1];
    const float* ws   = (const float*)d_in[2];
    const int*   oidx = (const int*)d_in[3];
    const float* ow   = (const float*)d_in[4];
    const float* bias = (const float*)d_in[5];
    float* out = (float*)d_out;

    cudaFuncSetAttribute(fused_kernel, cudaFuncAttributeMaxDynamicSharedMemorySize, SMEM_TOTAL);

    reset_kernel<<<1, 1>>>();
    fused_kernel<<<NCTA, 640, SMEM_TOTAL>>>(x, w, oidx, ow, bias, ws, out);
}

// round 16
// speedup vs baseline: 1.0793x; 1.0793x over previous
#include <cuda_runtime.h>
#include <cuda_bf16.h>
#include <cstdint>

#define TOK   256
#define INF   4096
#define OUTF  4096
#define NOUT  32

#define NCTA    296
#define NUNITS  4096            // (nt 64) x (mt 2) x (k 32)
#define STAGES  4

#define ABLK 16384              // A block: 128m x 128k int8, swizzled
#define BSZ  8192               // B block: 64n x 128k int8, swizzled
#define STG_SZ 24576
#define SA_OFF(s) ((s) * STG_SZ)
#define MBF_OFF  (STG_SZ * STAGES)   // 98304: full[4]
#define MBE_OFF  (MBF_OFF + 32)      // empty[4]
#define SMEM_TOTAL (MBF_OFF + 128)

// prologue scratch carved from dynamic stage-0/1 region (freed before pipeline)
#define P_OI   0                 // int[32]
#define P_RED  128               // float[8]
#define P_SC   160               // float
#define P_B    192               // float[128]
#define P_OWT  1024              // float[4096] (16KB)
#define P_XO   17408             // float[1024] (4KB)

// ---------------- scratch (no cudaMalloc allowed) ----------------
__device__ __align__(128) int8_t g_xq[TOK * INF];   // A blocks (1MB)
__device__ float g_xs[TOK];
__device__ int   g_qcnt;    // quantized rows done (0..256)
__device__ int   g_pfcnt;   // prefill blocks done (0..256)

__device__ __forceinline__ uint32_t smem_to_u32(const void* p) {
    uint32_t a;
    asm("{ .reg .u64 t; cvta.to.shared.u64 t, %1; cvt.u32.u64 %0, t; }" : "=r"(a) : "l"(p));
    return a;
}
__device__ __forceinline__ int ld_acq_gpu(const int* p) {
    int v; asm volatile("ld.acquire.gpu.global.s32 %0, [%1];" : "=r"(v) : "l"(p) : "memory"); return v;
}
__device__ __forceinline__ void red_rel_gpu(int* p, int v) {
    asm volatile("red.release.gpu.global.add.s32 [%0], %1;" :: "l"(p), "r"(v) : "memory");
}

#define MBARRIER_INIT(mbar, count) \
    asm volatile("mbarrier.init.shared.b64 [%0], %1;" :: "r"((uint32_t)(mbar)), "r"((uint32_t)(count)) : "memory")
#define MBARRIER_ARRIVE(mbar) \
    asm volatile("mbarrier.arrive.release.cta.shared.b64 _, [%0];" :: "r"((uint32_t)(mbar)) : "memory")
#define MBARRIER_EXPECT_TX(mbar, bytes) \
    asm volatile("mbarrier.arrive.expect_tx.shared.b64 _, [%0], %1;" :: "r"((uint32_t)(mbar)), "r"((uint32_t)(bytes)) : "memory")
#define BULK_G2S(dst, src, bytes, mbar) \
    asm volatile("cp.async.bulk.shared::cluster.global.mbarrier::complete_tx::bytes [%0], [%1], %2, [%3];" \
        :: "r"((uint32_t)(dst)), "l"(src), "r"((uint32_t)(bytes)), "r"((uint32_t)(mbar)) : "memory")
#define FENCE_PROXY_ASYNC() asm volatile("fence.proxy.async;" ::: "memory")

#define MBARRIER_WAIT_PARITY(mbar_smem_addr, phase_parity) do { \
    uint32_t _mbar = (uint32_t)(mbar_smem_addr); \
    uint32_t _parity = (uint32_t)(phase_parity); \
    uint32_t _done; \
    asm volatile("{\n\t.reg .pred p;\n\t" \
        "mbarrier.try_wait.parity.acquire.cta.shared::cta.b64 p, [%1], %2;\n\t" \
        "selp.b32 %0, 1, 0, p;\n\t}" : "=r"(_done) : "r"(_mbar), "r"(_parity) : "memory"); \
    if (!_done) { \
        asm volatile("{\n\t.reg .pred P1;\n\t" \
            "WAIT_LOOP_%=:\n\t" \
            "mbarrier.try_wait.parity.acquire.cta.shared::cta.b64 P1, [%0], %1, 0x989680;\n\t" \
            "@P1 bra.uni WAIT_DONE_%=;\n\t" \
            "bra.uni WAIT_LOOP_%=;\n\t" \
            "WAIT_DONE_%=:\n\t}" :: "r"(_mbar), "r"(_parity) : "memory"); \
    } \
} while (0)

// ---------------- reset counters (graph-replayed each launch) ----------------
__global__ void reset_kernel() { g_qcnt = 0; g_pfcnt = 0; }

// ---------------- fused persistent kernel ----------------
// 296 CTAs x 320 threads (10 warps), 2 CTAs/SM (all smem dynamic!).
// Warps 0-7: IMMA consumers (4m x 2n over m128 x n64). Warps 8-9: producers
// (warp 8 lane 0: TMA for A; each warp packs 32 B rows w->smem swizzled int8).
__global__ __launch_bounds__(320, 2) void fused_kernel(const float* __restrict__ x,
                                                       const int* __restrict__ w,
                                                       const int* __restrict__ oidx,
                                                       const float* __restrict__ ow,
                                                       const float* __restrict__ bias,
                                                       const float* __restrict__ wscale,
                                                       float* __restrict__ out) {
    extern __shared__ char smem[];
    const uint32_t sb = smem_to_u32(smem);
    const int tid = threadIdx.x;
    const int lane = tid & 31, wid = tid >> 5;
    const int bid = blockIdx.x;

    const int g0 = (int)(((long long)bid * NUNITS) / NCTA);
    const int g1 = (int)(((long long)(bid + 1) * NUNITS) / NCTA);
    const int nunits = g1 - g0;

    int*   s_oi  = (int*)(smem + P_OI);
    float* s_red = (float*)(smem + P_RED);
    float* s_sc  = (float*)(smem + P_SC);
    float* s_b   = (float*)(smem + P_B);
    float* s_owT = (float*)(smem + P_OWT);
    float* s_xo  = (float*)(smem + P_XO);

    if (tid == 0) {
#pragma unroll
        for (int s = 0; s < STAGES; s++) {
            MBARRIER_INIT(sb + MBF_OFF + s * 8, 3);    // 1 expect_tx + 2 pack-warp arrivals
            MBARRIER_INIT(sb + MBE_OFF + s * 8, 256);  // all consumer threads
        }
    }
    if (tid < NOUT) s_oi[tid] = oidx[tid];
    __syncthreads();

    // ================= prologue: CTAs 0..255 do 1 row + 1 block =================
    if (bid < TOK) {
        const int r = bid;
        float4 f[4];
        if (tid < 256) {
            const float4* xr = (const float4*)(x + (size_t)r * INF);
#pragma unroll
            for (int t = 0; t < 4; t++) f[t] = xr[tid * 4 + t];
            const int kbase = tid * 16;
            unsigned mz = 0;
#pragma unroll
            for (int j = 0; j < NOUT; j++) {
                unsigned d = (unsigned)(s_oi[j] - kbase);
                if (d < 16u) mz |= 1u << d;
            }
#pragma unroll
            for (int t = 0; t < 4; t++) {
                if (mz & (1u << (t * 4 + 0))) f[t].x = 0.0f;
                if (mz & (1u << (t * 4 + 1))) f[t].y = 0.0f;
                if (mz & (1u << (t * 4 + 2))) f[t].z = 0.0f;
                if (mz & (1u << (t * 4 + 3))) f[t].w = 0.0f;
            }
            float mx = 0.0f;
#pragma unroll
            for (int t = 0; t < 4; t++)
                mx = fmaxf(mx, fmaxf(fmaxf(fabsf(f[t].x), fabsf(f[t].y)),
                                     fmaxf(fabsf(f[t].z), fabsf(f[t].w))));
#pragma unroll
            for (int d = 16; d > 0; d >>= 1) mx = fmaxf(mx, __shfl_xor_sync(0xFFFFFFFFu, mx, d));
            if (lane == 0 && wid < 8) s_red[wid] = mx;
        }
        __syncthreads();
        if (tid == 0) {
            float m = s_red[0];
#pragma unroll
            for (int i = 1; i < 8; i++) m = fmaxf(m, s_red[i]);
            s_sc[0] = m;
            g_xs[r] = m;
        }
        __syncthreads();
        if (tid < 256) {
            const float r127 = 127.0f / fmaxf(s_sc[0], 1e-8f);
            uint32_t pk[4];
#pragma unroll
            for (int t = 0; t < 4; t++) {
                int q0 = min(max(__float2int_rn(f[t].x * r127), -127), 127);
                int q1 = min(max(__float2int_rn(f[t].y * r127), -127), 127);
                int q2 = min(max(__float2int_rn(f[t].z * r127), -127), 127);
                int q3 = min(max(__float2int_rn(f[t].w * r127), -127), 127);
                uint32_t p0 = __byte_perm((uint32_t)q0, (uint32_t)q1, 0x0040);
                uint32_t p1 = __byte_perm((uint32_t)q2, (uint32_t)q3, 0x0040);
                pk[t] = __byte_perm(p0, p1, 0x5410);
            }
            const int mt = r >> 7, rw = r & 127;
            const int cb = tid >> 3, cp = tid & 7;
            int8_t* dst = g_xq + ((size_t)(mt * 32 + cb) << 14) + rw * 128 + (((cp ^ (rw & 7))) << 4);
            *(uint4*)dst = make_uint4(pk[0], pk[1], pk[2], pk[3]);
        }
        __syncthreads();
        if (tid == 0) red_rel_gpu(&g_qcnt, 1);

        // ---- outlier + bias prefill block bid ----
        const int obase = (bid & 31) * 128;
        const int tbase = (bid >> 5) * 32;
        if (tid < 128) s_b[tid] = bias[obase + tid];
        if (tid < 256) {
#pragma unroll
            for (int t = 0; t < 4; t++) {
                int i = tid + t * 256;
                int o = i >> 3, j4 = i & 7;
                float4 fv = ((const float4*)ow)[(size_t)obase * 8 + i];
                s_owT[(j4 * 4 + 0) * 128 + o] = fv.x;
                s_owT[(j4 * 4 + 1) * 128 + o] = fv.y;
                s_owT[(j4 * 4 + 2) * 128 + o] = fv.z;
                s_owT[(j4 * 4 + 3) * 128 + o] = fv.w;
            }
#pragma unroll
            for (int t = 0; t < 4; t++) {
                int i = tid + t * 256;
                int rr = i >> 5, j = i & 31;
                s_xo[i] = x[(size_t)(tbase + rr) * INF + s_oi[j]];
            }
        }
        __syncthreads();
        if (tid < 256) {
            const int ty = tid >> 5, tx = tid & 31;
            float acc[4][4];
#pragma unroll
            for (int tt = 0; tt < 4; tt++)
#pragma unroll
                for (int c = 0; c < 4; c++) acc[tt][c] = s_b[tx + c * 32];
#pragma unroll
            for (int j = 0; j < NOUT; j++) {
                float wv[4];
#pragma unroll
                for (int c = 0; c < 4; c++) wv[c] = s_owT[j * 128 + tx + c * 32];
#pragma unroll
                for (int tt = 0; tt < 4; tt++) {
                    float xv = s_xo[(ty * 4 + tt) * NOUT + j];
#pragma unroll
                    for (int c = 0; c < 4; c++) acc[tt][c] += xv * wv[c];
                }
            }
#pragma unroll
            for (int tt = 0; tt < 4; tt++)
#pragma unroll
                for (int c = 0; c < 4; c++)
                    out[(size_t)(tbase + ty * 4 + tt) * OUTF + obase + tx + c * 32] = acc[tt][c];
        }
        __syncthreads();
        if (tid == 0) red_rel_gpu(&g_pfcnt, 1);
    }
    __syncthreads();   // prologue scratch (stage-0/1 region) free from here

    // ================= main phase =================
    if (wid >= 8) {
        // ---- producer warps 8-9: A via TMA (w8 l0), B packed 32 rows/warp ----
        const int rbase = (wid - 8) * 32;
        if (wid == 8 && lane == 0) {
            while (ld_acq_gpu(&g_qcnt) != TOK) __nanosleep(64);
        }
        __syncwarp();
        FENCE_PROXY_ASYNC();

        const uint32_t lcol = ((uint32_t)lane & 3) * 4;
        const uint32_t lgrp = (uint32_t)lane >> 2;

#pragma unroll 1
        for (int it = 0; it < nunits; it++) {
            const int g = g0 + it;
            const int fs = it & (STAGES - 1);
            const int tile = g >> 5, k = g & 31;
            const int nt = tile >> 1, mt = tile & 1;
            if (it >= STAGES) {
                if (lane == 0) MBARRIER_WAIT_PARITY(sb + MBE_OFF + fs * 8, ((it >> 2) - 1) & 1);
                __syncwarp();
            }
            const uint32_t mb = sb + MBF_OFF + fs * 8;
            if (wid == 8 && lane == 0) {
                MBARRIER_EXPECT_TX(mb, ABLK);
                BULK_G2S(sb + SA_OFF(fs), g_xq + ((size_t)(mt * 32 + k) << 14), ABLK, mb);
            }
            // pack this warp's 32 B rows: 2 batches of (16 LDG.128 -> 16 STS.32)
            const int* wsrc = w + (size_t)(nt * 64 + rbase) * INF + k * 128;
            const uint32_t bstage = sb + SA_OFF(fs) + ABLK;
#pragma unroll 1
            for (int rb = 0; rb < 32; rb += 16) {
                int4 v[16];
#pragma unroll
                for (int i = 0; i < 16; i++)
                    v[i] = ((const int4*)(wsrc + (size_t)(rb + i) * INF))[lane];
#pragma unroll
                for (int i = 0; i < 16; i++) {
                    const int r = rbase + rb + i;
                    uint32_t pk = __byte_perm(
                        __byte_perm((uint32_t)v[i].x, (uint32_t)v[i].y, 0x0040),
                        __byte_perm((uint32_t)v[i].z, (uint32_t)v[i].w, 0x0040), 0x5410);
                    uint32_t off = (uint32_t)r * 128 + ((lgrp ^ (uint32_t)(r & 7)) << 4) + lcol;
                    asm volatile("st.shared.b32 [%0], %1;" :: "r"(bstage + off), "r"(pk) : "memory");
                }
            }
            __syncwarp();
            if (lane == 0) MBARRIER_ARRIVE(mb);   // release: this warp's STS visible at flip
        }
    } else {
        // ---- consumers: proven R11 core, 8 warps (4m x 2n over m128 x n64) ----
        const int wm = wid >> 1, wn = wid & 1;
        const float inv = 1.0f / 16129.0f;
        const int grp = lane >> 2, qid = lane & 3;
        bool pfok = false;

        int acc[2][4][4];
#pragma unroll
        for (int i = 0; i < 2; i++)
#pragma unroll
            for (int j = 0; j < 4; j++)
#pragma unroll
                for (int q = 0; q < 4; q++) acc[i][j][q] = 0;

#pragma unroll 1
        for (int c = 0; c < nunits; c++) {
            const int g = g0 + c;
            const int s = c & (STAGES - 1);
            MBARRIER_WAIT_PARITY(sb + MBF_OFF + s * 8, (c >> 2) & 1);

#pragma unroll
            for (int ksl = 0; ksl < 4; ksl++) {
                uint32_t a[2][4];
#pragma unroll
                for (int mf = 0; mf < 2; mf++) {
                    int row = wm * 32 + mf * 16 + (lane & 15);
                    int kc = 2 * ksl + (lane >> 4);
                    uint32_t ad = sb + SA_OFF(s) +
                                  (uint32_t)(row * 128 + ((kc ^ (row & 7)) << 4));
                    asm volatile("ldmatrix.sync.aligned.m8n8.x4.shared.b16 {%0,%1,%2,%3}, [%4];"
                        : "=r"(a[mf][0]), "=r"(a[mf][1]), "=r"(a[mf][2]), "=r"(a[mf][3])
                        : "r"(ad));
                }
                uint32_t b[2][4];
#pragma unroll
                for (int np = 0; np < 2; np++) {
                    int n = wn * 32 + np * 16 + (lane & 7) + ((lane >> 4) << 3);
                    int kc = 2 * ksl + ((lane >> 3) & 1);
                    uint32_t bd = sb + SA_OFF(s) + ABLK +
                                  (uint32_t)(n * 128 + ((kc ^ (n & 7)) << 4));
                    asm volatile("ldmatrix.sync.aligned.m8n8.x4.shared.b16 {%0,%1,%2,%3}, [%4];"
                        : "=r"(b[np][0]), "=r"(b[np][1]), "=r"(b[np][2]), "=r"(b[np][3])
                        : "r"(bd));
                }
#pragma unroll
                for (int mf = 0; mf < 2; mf++)
#pragma unroll
                    for (int nf = 0; nf < 4; nf++) {
                        uint32_t b0 = b[nf >> 1][(nf & 1) * 2];
                        uint32_t b1 = b[nf >> 1][(nf & 1) * 2 + 1];
                        asm volatile(
                            "mma.sync.aligned.m16n8k32.row.col.s32.s8.s8.s32 "
                            "{%0,%1,%2,%3}, {%4,%5,%6,%7}, {%8,%9}, {%0,%1,%2,%3};"
                            : "+r"(acc[mf][nf][0]), "+r"(acc[mf][nf][1]),
                              "+r"(acc[mf][nf][2]), "+r"(acc[mf][nf][3])
                            : "r"(a[mf][0]), "r"(a[mf][1]), "r"(a[mf][2]), "r"(a[mf][3]),
                              "r"(b0), "r"(b1));
                    }
            }
            MBARRIER_ARRIVE(sb + MBE_OFF + s * 8);

            // ---- epilogue at tile boundary or range end ----
            if (c + 1 == nunits || ((g + 1) & 31) == 0) {
                if (!pfok) {
                    while (ld_acq_gpu(&g_pfcnt) != TOK) __nanosleep(64);
                    pfok = true;
                }
                const int tile = g >> 5;
                const int nbase = (tile >> 1) * 64, mbase = (tile & 1) * 128;
#pragma unroll
                for (int mf = 0; mf < 2; mf++) {
                    const int m0 = mbase + wm * 32 + mf * 16 + grp;
                    const float s0 = g_xs[m0] * inv;
                    const float s1 = g_xs[m0 + 8] * inv;
#pragma unroll
                    for (int nf = 0; nf < 4; nf++) {
                        const int o = nbase + wn * 32 + nf * 8 + qid * 2;
                        const float2 wsv = *(const float2*)(wscale + o);
                        float* p0 = out + (size_t)m0 * OUTF + o;
                        float* p1 = out + (size_t)(m0 + 8) * OUTF + o;
                        atomicAdd(p0,     (float)acc[mf][nf][0] * (s0 * wsv.x));
                        atomicAdd(p0 + 1, (float)acc[mf][nf][1] * (s0 * wsv.y));
                        atomicAdd(p1,     (float)acc[mf][nf][2] * (s1 * wsv.x));
                        atomicAdd(p1 + 1, (float)acc[mf][nf][3] * (s1 * wsv.y));
                    }
                }
#pragma unroll
                for (int i = 0; i < 2; i++)
#pragma unroll
                    for (int j = 0; j < 4; j++)
#pragma unroll
                        for (int q = 0; q < 4; q++) acc[i][j][q] = 0;
            }
        }
    }
}

// ---------------- launch ----------------
extern "C" void kernel_launch(void* const* d_in, const int* in_sizes, int n_in,
                              void* d_out, int out_size) {
    const float* x    = (const float*)d_in[0];
    const int*   w    = (const int*)d_in[1];
    const float* ws   = (const float*)d_in[2];
    const int*   oidx = (const int*)d_in[3];
    const float* ow   = (const float*)d_in[4];
    const float* bias = (const float*)d_in[5];
    float* out = (float*)d_out;

    cudaFuncSetAttribute(fused_kernel, cudaFuncAttributeMaxDynamicSharedMemorySize, SMEM_TOTAL);

    reset_kernel<<<1, 1>>>();
    fused_kernel<<<NCTA, 320, SMEM_TOTAL>>>(x, w, oidx, ow, bias, ws, out);
}